// round 10
// baseline (speedup 1.0000x reference)
#include <cuda_runtime.h>
#include <cuda_bf16.h>
#include <math.h>

// Problem constants (B, N, M, C, S = 4, 16384, 128, 128, 512)
#define BB    4
#define NPTS  16384
#define MBOX  128
#define CFEAT 128
#define SSAMP 512
#define ROWW  (3 + CFEAT)            // 131 floats per pooled row
#define NBOX  (BB * MBOX)            // 512
#define BOXFLOATS (SSAMP * ROWW)     // 67072 floats per box tile

#define NTHREADS 512
#define NWARPS   (NTHREADS / 32)     // 16
#define SEG      (NPTS / NWARPS)     // 1024 points per warp segment
#define P1ITERS  (SEG / 128)         // 8 iters, 128 points (4/lane) each

// ---- Per-distinct-row register context: loaded+shuffled ONCE, reused by all dups.
struct RowRegs {
    float4 fv;                 // lane's f[4l .. 4l+3]
    float  pc;                 // lane<3: coord
    float  uy, uz, uw;         // lane (l-1)'s fv.y/z/w
    float  c0, c1, c2;         // coord broadcasts (lane-0 hole fill)
    float  ty, tz, tw;         // lane 31's fv.y/z/w (tail f[125..127])
};

__device__ __forceinline__ RowRegs prepare_row(const float* __restrict__ f,
                                               const float* __restrict__ p,
                                               int lane)
{
    RowRegs r;
    r.fv = __ldg((const float4*)f + lane);
    r.pc = 0.0f;
    if (lane < 3) r.pc = __ldg(p + lane);
    r.uy = __shfl_up_sync(0xffffffffu, r.fv.y, 1);
    r.uz = __shfl_up_sync(0xffffffffu, r.fv.z, 1);
    r.uw = __shfl_up_sync(0xffffffffu, r.fv.w, 1);
    r.c0 = __shfl_sync(0xffffffffu, r.pc, 0);
    r.c1 = __shfl_sync(0xffffffffu, r.pc, 1);
    r.c2 = __shfl_sync(0xffffffffu, r.pc, 2);
    r.ty = __shfl_sync(0xffffffffu, r.fv.y, 31);
    r.tz = __shfl_sync(0xffffffffu, r.fv.z, 31);
    r.tw = __shfl_sync(0xffffffffu, r.fv.w, 31);
    return r;
}

// ---- One duplicate store: PAD lead scalars + 32 aligned float4 + (3-PAD) tail.
// Pure selects + stores; no shuffles.
template<int PAD>
__device__ __forceinline__ void store_dup(float* __restrict__ o, int rbase,
                                          const RowRegs& r, int lane)
{
    const bool l0 = (lane == 0);
    if (PAD > 0 && lane < PAD)
        __stcs(o + rbase + lane, r.pc);

    float4 v;
    if (PAD == 0) {
        v.x = l0 ? r.c0 : r.uy;
        v.y = l0 ? r.c1 : r.uz;
        v.z = l0 ? r.c2 : r.uw;
        v.w = r.fv.x;
    } else if (PAD == 1) {
        v.x = l0 ? r.c1 : r.uz;
        v.y = l0 ? r.c2 : r.uw;
        v.z = r.fv.x;
        v.w = r.fv.y;
    } else if (PAD == 2) {
        v.x = l0 ? r.c2 : r.uw;
        v.y = r.fv.x;
        v.z = r.fv.y;
        v.w = r.fv.z;
    } else {
        v = r.fv;
    }
    __stcs((float4*)(o + rbase + PAD) + lane, v);

    if (PAD < 3) {
        float tv;
        if (PAD == 0)      tv = (lane == 0) ? r.ty : (lane == 1) ? r.tz : r.tw;
        else if (PAD == 1) tv = (lane == 0) ? r.tz : r.tw;
        else               tv = r.tw;
        if (lane < 3 - PAD)
            __stcs(o + rbase + PAD + 128 + lane, tv);
    }
}

__device__ __forceinline__ void store_dup_dispatch(float* __restrict__ o, int rbase,
                                                   const RowRegs& r, int lane)
{
    switch ((4 - (rbase & 3)) & 3) {   // warp-uniform
    case 0:  store_dup<0>(o, rbase, r, lane); break;
    case 1:  store_dup<1>(o, rbase, r, lane); break;
    case 2:  store_dup<2>(o, rbase, r, lane); break;
    default: store_dup<3>(o, rbase, r, lane); break;
    }
}

__global__ __launch_bounds__(NTHREADS, 4)   // 4 CTAs/SM, single wave over grid=512
void roipool3d_kernel(const float* __restrict__ points,   // (B, N, 3)
                      const float* __restrict__ feats,    // (B, N, C)
                      const float* __restrict__ boxes,    // (B, M, 7)
                      float* __restrict__ out,            // (B,M,S,131) then flags (B,M)
                      long long flag_off)
{
    const int bm = blockIdx.x;
    const int b  = bm >> 7;

    // --- Box parameters ---
    const float* box = boxes + (size_t)bm * 7;
    const float cx = box[0];
    const float cy = box[1];
    const float dz = box[5];
    const float cz = box[2] + 0.5f * dz;
    const float dx = box[3];
    const float dy = box[4];
    const float rz = box[6];
    const float cosa = cosf(-rz);
    const float sina = sinf(-rz);
    const float hx = 0.5f * dx;
    const float hy = 0.5f * dy;
    const float hz = 0.5f * dz;

    __shared__ int s_buf[NWARPS][SSAMP];   // 32 KB: per-warp ordered buffers
    __shared__ int s_cnt[NWARPS];
    __shared__ int s_src[SSAMP];           // wrap-resolved source index per row

    const int tid  = threadIdx.x;
    const int wid  = tid >> 5;
    const int lane = tid & 31;
    const unsigned lmask_lt = (1u << lane) - 1u;

    const float* pts = points + (size_t)b * NPTS * 3;

    // --- Phase 1: float4 loads, 4 points per lane, ordered compaction ---
    {
        const int seg_start = wid * SEG;
        const float4* g4 = (const float4*)(pts + seg_start * 3);  // 16B-aligned
        int wcnt = 0;

        #pragma unroll 2
        for (int it = 0; it < P1ITERS; ++it) {
            // lane handles points base+4l .. base+4l+3 (lane-major: order preserved)
            const float4 A  = __ldg(g4 + it * 96 + 3 * lane + 0);  // x0 y0 z0 x1
            const float4 Bv = __ldg(g4 + it * 96 + 3 * lane + 1);  // y1 z1 x2 y2
            const float4 Cv = __ldg(g4 + it * 96 + 3 * lane + 2);  // z2 x3 y3 z3

            bool m0, m1, m2, m3;
            {
                #define BOXTEST(PX, PY, PZ, OUTM) do {                        \
                    const float sx = (PX) - cx;                               \
                    const float sy = (PY) - cy;                               \
                    const float lx = sx * cosa - sy * sina;                   \
                    const float ly = sx * sina + sy * cosa;                   \
                    OUTM = (fabsf((PZ) - cz) <= hz) &&                        \
                           (fabsf(lx) < hx) && (fabsf(ly) < hy);              \
                } while (0)
                BOXTEST(A.x,  A.y,  A.z,  m0);
                BOXTEST(A.w,  Bv.x, Bv.y, m1);
                BOXTEST(Bv.z, Bv.w, Cv.x, m2);
                BOXTEST(Cv.y, Cv.z, Cv.w, m3);
                #undef BOXTEST
            }

            const unsigned b0 = __ballot_sync(0xffffffffu, m0);
            const unsigned b1 = __ballot_sync(0xffffffffu, m1);
            const unsigned b2 = __ballot_sync(0xffffffffu, m2);
            const unsigned b3 = __ballot_sync(0xffffffffu, m3);

            const int pre = __popc(b0 & lmask_lt) + __popc(b1 & lmask_lt)
                          + __popc(b2 & lmask_lt) + __popc(b3 & lmask_lt);
            const int idx = seg_start + it * 128 + 4 * lane;

            int rk = wcnt + pre;
            if (m0 && rk < SSAMP) s_buf[wid][rk] = idx + 0;
            rk += m0;
            if (m1 && rk < SSAMP) s_buf[wid][rk] = idx + 1;
            rk += m1;
            if (m2 && rk < SSAMP) s_buf[wid][rk] = idx + 2;
            rk += m2;
            if (m3 && rk < SSAMP) s_buf[wid][rk] = idx + 3;

            wcnt += __popc(b0) + __popc(b1) + __popc(b2) + __popc(b3);
        }
        if (lane == 0) s_cnt[wid] = wcnt;
    }
    __syncthreads();

    // --- Merge + wrap resolution ---
    int total = 0;
    int off   = 0;
    #pragma unroll
    for (int w = 0; w < NWARPS; ++w) {
        const int c = s_cnt[w];
        off   += (w < wid) ? c : 0;
        total += c;
    }
    const int cnt = total;
    {
        const int stored = min(s_cnt[wid], SSAMP);
        for (int k = lane; k < stored; k += 32) {
            const int g = off + k;
            if (g < SSAMP) s_src[g] = s_buf[wid][k];
        }
    }
    __syncthreads();
    if (cnt > 0 && cnt < SSAMP) {
        for (int s = cnt + tid; s < SSAMP; s += NTHREADS)
            s_src[s] = s_src[s % cnt];
        __syncthreads();
    }

    // --- Phase 2 ---
    float* o = out + (size_t)bm * BOXFLOATS;

    if (cnt == 0) {
        float4 z = make_float4(0.f, 0.f, 0.f, 0.f);
        float4* o4 = (float4*)o;
        for (int i = tid; i < BOXFLOATS / 4; i += NTHREADS)
            __stcs(o4 + i, z);
    } else if (cnt >= NWARPS) {
        // Distinct-source mapping: prepare each row ONCE, store all duplicates.
        const float* fbase = feats + (size_t)b * NPTS * CFEAT;
        const int jmax = min(cnt, SSAMP);
        for (int j = wid; j < jmax; j += NWARPS) {
            const int src = s_src[j];
            const RowRegs r = prepare_row(fbase + (size_t)src * CFEAT,
                                          pts + src * 3, lane);
            for (int s = j; s < SSAMP; s += cnt)
                store_dup_dispatch(o, s * ROWW, r, lane);
        }
    } else {
        // Few distinct rows: per-row mapping keeps all 16 warps busy (L1-resident).
        const float* fbase = feats + (size_t)b * NPTS * CFEAT;
        for (int s = wid; s < SSAMP; s += NWARPS) {
            const int src = s_src[s];
            const RowRegs r = prepare_row(fbase + (size_t)src * CFEAT,
                                          pts + src * 3, lane);
            store_dup_dispatch(o, s * ROWW, r, lane);
        }
    }

    // --- Empty flag ---
    if (tid == 0)
        out[flag_off + bm] = (cnt == 0) ? 1.0f : 0.0f;
}

extern "C" void kernel_launch(void* const* d_in, const int* in_sizes, int n_in,
                              void* d_out, int out_size)
{
    const float* points = (const float*)d_in[0];   // (B, N, 3)
    const float* feats  = (const float*)d_in[1];   // (B, N, C)
    const float* boxes  = (const float*)d_in[2];   // (B, M, 7)
    float* out = (float*)d_out;

    const long long flag_off = (long long)out_size - (long long)NBOX;

    roipool3d_kernel<<<NBOX, NTHREADS>>>(points, feats, boxes, out, flag_off);
}

// round 13
// speedup vs baseline: 1.1245x; 1.1245x over previous
#include <cuda_runtime.h>
#include <cuda_bf16.h>
#include <math.h>

// Problem constants (B, N, M, C, S = 4, 16384, 128, 128, 512)
#define BB    4
#define NPTS  16384
#define MBOX  128
#define CFEAT 128
#define SSAMP 512
#define ROWW  (3 + CFEAT)            // 131 floats per pooled row
#define NBOX  (BB * MBOX)            // 512
#define BOXFLOATS (SSAMP * ROWW)     // 67072 floats per box tile

#define NTHREADS 512
#define NWARPS   (NTHREADS / 32)     // 16
#define SEG      (NPTS / NWARPS)     // 1024
#define ITERS    (SEG / 32)          // 32

// ---- Lean per-distinct-row context (11 regs live across the dup loop).
// e1..e3 have the lane-0 coordinate holes pre-merged.
struct RowCtx {
    float4 fv;           // lane's f[4l .. 4l+3]
    float  pc;           // lane<3: own coord (for lead scalars)
    float  e1, e2, e3;   // lane(l-1).fv.{y,z,w}, lane0 = coord{0,1,2}
    float  ty, tz, tw;   // lane31.fv.{y,z,w}  (tail f[125..127])
};

__device__ __forceinline__ RowCtx prepare_row(const float* __restrict__ f,
                                              const float* __restrict__ p,
                                              int lane)
{
    RowCtx r;
    r.fv = __ldg((const float4*)f + lane);
    r.pc = 0.0f;
    if (lane < 3) r.pc = __ldg(p + lane);

    const float uy = __shfl_up_sync(0xffffffffu, r.fv.y, 1);
    const float uz = __shfl_up_sync(0xffffffffu, r.fv.z, 1);
    const float uw = __shfl_up_sync(0xffffffffu, r.fv.w, 1);
    const float c0 = __shfl_sync(0xffffffffu, r.pc, 0);
    const float c1 = __shfl_sync(0xffffffffu, r.pc, 1);
    const float c2 = __shfl_sync(0xffffffffu, r.pc, 2);
    const bool l0 = (lane == 0);
    r.e1 = l0 ? c0 : uy;
    r.e2 = l0 ? c1 : uz;
    r.e3 = l0 ? c2 : uw;
    r.ty = __shfl_sync(0xffffffffu, r.fv.y, 31);
    r.tz = __shfl_sync(0xffffffffu, r.fv.z, 31);
    r.tw = __shfl_sync(0xffffffffu, r.fv.w, 31);
    return r;
}

// ---- One duplicate store: PAD lead scalars + 32 aligned float4 + (3-PAD) tail.
// No shuffles, no selects (all pre-merged): pure register moves + stores.
template<int PAD>
__device__ __forceinline__ void store_dup(float* __restrict__ o, int rbase,
                                          const RowCtx& r, int lane)
{
    if (PAD > 0 && lane < PAD)
        __stcs(o + rbase + lane, r.pc);

    float4 v;
    if (PAD == 0) {
        v.x = r.e1; v.y = r.e2; v.z = r.e3; v.w = r.fv.x;
    } else if (PAD == 1) {
        v.x = r.e2; v.y = r.e3; v.z = r.fv.x; v.w = r.fv.y;
    } else if (PAD == 2) {
        v.x = r.e3; v.y = r.fv.x; v.z = r.fv.y; v.w = r.fv.z;
    } else {
        v = r.fv;
    }
    __stcs((float4*)(o + rbase + PAD) + lane, v);

    if (PAD < 3) {
        float tv;
        if (PAD == 0)      tv = (lane == 0) ? r.ty : (lane == 1) ? r.tz : r.tw;
        else if (PAD == 1) tv = (lane == 0) ? r.tz : r.tw;
        else               tv = r.tw;
        if (lane < 3 - PAD)
            __stcs(o + rbase + PAD + 128 + lane, tv);
    }
}

__device__ __forceinline__ void store_dup_dispatch(float* __restrict__ o, int rbase,
                                                   const RowCtx& r, int lane)
{
    switch ((4 - (rbase & 3)) & 3) {   // warp-uniform
    case 0:  store_dup<0>(o, rbase, r, lane); break;
    case 1:  store_dup<1>(o, rbase, r, lane); break;
    case 2:  store_dup<2>(o, rbase, r, lane); break;
    default: store_dup<3>(o, rbase, r, lane); break;
    }
}

__global__ __launch_bounds__(NTHREADS, 4)   // 4 CTAs/SM, single wave over grid=512
void roipool3d_kernel(const float* __restrict__ points,   // (B, N, 3)
                      const float* __restrict__ feats,    // (B, N, C)
                      const float* __restrict__ boxes,    // (B, M, 7)
                      float* __restrict__ out,            // (B,M,S,131) then flags (B,M)
                      long long flag_off)
{
    const int bm = blockIdx.x;
    const int b  = bm >> 7;

    // --- Box parameters ---
    const float* box = boxes + (size_t)bm * 7;
    const float cx = box[0];
    const float cy = box[1];
    const float dz = box[5];
    const float cz = box[2] + 0.5f * dz;
    const float dx = box[3];
    const float dy = box[4];
    const float rz = box[6];
    const float cosa = cosf(-rz);
    const float sina = sinf(-rz);
    const float hx = 0.5f * dx;
    const float hy = 0.5f * dy;
    const float hz = 0.5f * dz;

    __shared__ int s_buf[NWARPS][SSAMP];   // 32 KB: per-warp ordered buffers
    __shared__ int s_cnt[NWARPS];
    __shared__ int s_src[SSAMP];           // wrap-resolved source index per row

    const int tid  = threadIdx.x;
    const int wid  = tid >> 5;
    const int lane = tid & 31;
    const unsigned lmask_lt = (1u << lane) - 1u;

    const float* pts = points + (size_t)b * NPTS * 3;

    // --- Phase 1: warp-autonomous ordered compaction (R9 verbatim) ---
    {
        const int seg_start = wid * SEG;
        int wcnt = 0;

        #pragma unroll 8
        for (int it = 0; it < ITERS; ++it) {
            const int i = seg_start + it * 32 + lane;
            const float px = pts[i * 3 + 0];
            const float py = pts[i * 3 + 1];
            const float pz = pts[i * 3 + 2];

            const float sx = px - cx;
            const float sy = py - cy;
            const float lx = sx * cosa - sy * sina;
            const float ly = sx * sina + sy * cosa;

            const bool in =
                (fabsf(pz - cz) <= hz) &&
                (fabsf(lx) < hx) &&
                (fabsf(ly) < hy);

            const unsigned ball = __ballot_sync(0xffffffffu, in);
            const int r = wcnt + __popc(ball & lmask_lt);
            if (in && r < SSAMP) s_buf[wid][r] = i;
            wcnt += __popc(ball);
        }
        if (lane == 0) s_cnt[wid] = wcnt;
    }
    __syncthreads();

    // --- Merge + wrap resolution ---
    int total = 0;
    int off   = 0;
    #pragma unroll
    for (int w = 0; w < NWARPS; ++w) {
        const int c = s_cnt[w];
        off   += (w < wid) ? c : 0;
        total += c;
    }
    const int cnt = total;
    {
        const int stored = min(s_cnt[wid], SSAMP);
        for (int k = lane; k < stored; k += 32) {
            const int g = off + k;
            if (g < SSAMP) s_src[g] = s_buf[wid][k];
        }
    }
    __syncthreads();
    if (cnt > 0 && cnt < SSAMP) {
        for (int s = cnt + tid; s < SSAMP; s += NTHREADS)
            s_src[s] = s_src[s % cnt];
        __syncthreads();
    }

    // --- Phase 2 ---
    float* o = out + (size_t)bm * BOXFLOATS;

    if (cnt == 0) {
        float4 z = make_float4(0.f, 0.f, 0.f, 0.f);
        float4* o4 = (float4*)o;
        for (int i = tid; i < BOXFLOATS / 4; i += NTHREADS)
            __stcs(o4 + i, z);
    } else if (cnt >= NWARPS) {
        // Distinct-source mapping: prepare each row ONCE, store all duplicates.
        const float* fbase = feats + (size_t)b * NPTS * CFEAT;
        const int jmax = min(cnt, SSAMP);
        for (int j = wid; j < jmax; j += NWARPS) {
            const int src = s_src[j];
            const RowCtx r = prepare_row(fbase + (size_t)src * CFEAT,
                                         pts + src * 3, lane);
            for (int s = j; s < SSAMP; s += cnt)
                store_dup_dispatch(o, s * ROWW, r, lane);
        }
    } else {
        // Few distinct rows: per-row mapping keeps all 16 warps busy (L1-resident).
        const float* fbase = feats + (size_t)b * NPTS * CFEAT;
        for (int s = wid; s < SSAMP; s += NWARPS) {
            const int src = s_src[s];
            const RowCtx r = prepare_row(fbase + (size_t)src * CFEAT,
                                         pts + src * 3, lane);
            store_dup_dispatch(o, s * ROWW, r, lane);
        }
    }

    // --- Empty flag ---
    if (tid == 0)
        out[flag_off + bm] = (cnt == 0) ? 1.0f : 0.0f;
}

extern "C" void kernel_launch(void* const* d_in, const int* in_sizes, int n_in,
                              void* d_out, int out_size)
{
    const float* points = (const float*)d_in[0];   // (B, N, 3)
    const float* feats  = (const float*)d_in[1];   // (B, N, C)
    const float* boxes  = (const float*)d_in[2];   // (B, M, 7)
    float* out = (float*)d_out;

    const long long flag_off = (long long)out_size - (long long)NBOX;

    roipool3d_kernel<<<NBOX, NTHREADS>>>(points, feats, boxes, out, flag_off);
}

// round 14
// speedup vs baseline: 1.1286x; 1.0037x over previous
#include <cuda_runtime.h>
#include <cuda_bf16.h>
#include <math.h>

// Problem constants (B, N, M, C, S = 4, 16384, 128, 128, 512)
#define BB    4
#define NPTS  16384
#define MBOX  128
#define CFEAT 128
#define SSAMP 512
#define ROWW  (3 + CFEAT)            // 131 floats per pooled row
#define NBOX  (BB * MBOX)            // 512
#define BOXFLOATS (SSAMP * ROWW)     // 67072 floats per box tile

#define NTHREADS 384
#define NWARPS   (NTHREADS / 32)     // 12
// Uneven contiguous segments: warps 0-7 scan 1376 pts (43 iters),
// warps 8-11 scan 1344 pts (42 iters). 8*1376 + 4*1344 = 16384.
#define SEG_BIG   1376
#define SEG_SMALL 1344

// ---- Lean per-distinct-row context. e1..e3 have lane-0 coord holes pre-merged.
struct RowCtx {
    float4 fv;           // lane's f[4l .. 4l+3]
    float  pc;           // lane<3: own coord (for lead scalars)
    float  e1, e2, e3;   // lane(l-1).fv.{y,z,w}, lane0 = coord{0,1,2}
    float  ty, tz, tw;   // lane31.fv.{y,z,w}  (tail f[125..127])
};

__device__ __forceinline__ RowCtx prepare_row(const float* __restrict__ f,
                                              const float* __restrict__ p,
                                              int lane)
{
    RowCtx r;
    r.fv = __ldg((const float4*)f + lane);
    r.pc = 0.0f;
    if (lane < 3) r.pc = __ldg(p + lane);

    const float uy = __shfl_up_sync(0xffffffffu, r.fv.y, 1);
    const float uz = __shfl_up_sync(0xffffffffu, r.fv.z, 1);
    const float uw = __shfl_up_sync(0xffffffffu, r.fv.w, 1);
    const float c0 = __shfl_sync(0xffffffffu, r.pc, 0);
    const float c1 = __shfl_sync(0xffffffffu, r.pc, 1);
    const float c2 = __shfl_sync(0xffffffffu, r.pc, 2);
    const bool l0 = (lane == 0);
    r.e1 = l0 ? c0 : uy;
    r.e2 = l0 ? c1 : uz;
    r.e3 = l0 ? c2 : uw;
    r.ty = __shfl_sync(0xffffffffu, r.fv.y, 31);
    r.tz = __shfl_sync(0xffffffffu, r.fv.z, 31);
    r.tw = __shfl_sync(0xffffffffu, r.fv.w, 31);
    return r;
}

// ---- One duplicate store: PAD lead scalars + 32 aligned float4 + (3-PAD) tail.
template<int PAD>
__device__ __forceinline__ void store_dup(float* __restrict__ o, int rbase,
                                          const RowCtx& r, int lane)
{
    if (PAD > 0 && lane < PAD)
        __stcs(o + rbase + lane, r.pc);

    float4 v;
    if (PAD == 0) {
        v.x = r.e1; v.y = r.e2; v.z = r.e3; v.w = r.fv.x;
    } else if (PAD == 1) {
        v.x = r.e2; v.y = r.e3; v.z = r.fv.x; v.w = r.fv.y;
    } else if (PAD == 2) {
        v.x = r.e3; v.y = r.fv.x; v.z = r.fv.y; v.w = r.fv.z;
    } else {
        v = r.fv;
    }
    __stcs((float4*)(o + rbase + PAD) + lane, v);

    if (PAD < 3) {
        float tv;
        if (PAD == 0)      tv = (lane == 0) ? r.ty : (lane == 1) ? r.tz : r.tw;
        else if (PAD == 1) tv = (lane == 0) ? r.tz : r.tw;
        else               tv = r.tw;
        if (lane < 3 - PAD)
            __stcs(o + rbase + PAD + 128 + lane, tv);
    }
}

__device__ __forceinline__ void store_dup_dispatch(float* __restrict__ o, int rbase,
                                                   const RowCtx& r, int lane)
{
    switch ((4 - (rbase & 3)) & 3) {   // warp-uniform
    case 0:  store_dup<0>(o, rbase, r, lane); break;
    case 1:  store_dup<1>(o, rbase, r, lane); break;
    case 2:  store_dup<2>(o, rbase, r, lane); break;
    default: store_dup<3>(o, rbase, r, lane); break;
    }
}

__global__ __launch_bounds__(NTHREADS, 4)   // 4 CTAs/SM, single wave, 42-reg budget
void roipool3d_kernel(const float* __restrict__ points,   // (B, N, 3)
                      const float* __restrict__ feats,    // (B, N, C)
                      const float* __restrict__ boxes,    // (B, M, 7)
                      float* __restrict__ out,            // (B,M,S,131) then flags (B,M)
                      long long flag_off)
{
    const int bm = blockIdx.x;
    const int b  = bm >> 7;

    // --- Box parameters ---
    const float* box = boxes + (size_t)bm * 7;
    const float cx = box[0];
    const float cy = box[1];
    const float dz = box[5];
    const float cz = box[2] + 0.5f * dz;
    const float dx = box[3];
    const float dy = box[4];
    const float rz = box[6];
    const float cosa = cosf(-rz);
    const float sina = sinf(-rz);
    const float hx = 0.5f * dx;
    const float hy = 0.5f * dy;
    const float hz = 0.5f * dz;

    __shared__ int s_buf[NWARPS][SSAMP];   // 24 KB: per-warp ordered buffers
    __shared__ int s_cnt[NWARPS];
    __shared__ int s_src[SSAMP];           // wrap-resolved source index per row

    const int tid  = threadIdx.x;
    const int wid  = tid >> 5;
    const int lane = tid & 31;
    const unsigned lmask_lt = (1u << lane) - 1u;

    const float* pts = points + (size_t)b * NPTS * 3;

    // --- Phase 1: warp-autonomous ordered compaction, uneven contiguous segs ---
    {
        const int seg_start = (wid < 8) ? wid * SEG_BIG
                                        : 8 * SEG_BIG + (wid - 8) * SEG_SMALL;
        const int iters = (wid < 8) ? (SEG_BIG / 32) : (SEG_SMALL / 32);
        int wcnt = 0;

        #pragma unroll 4
        for (int it = 0; it < iters; ++it) {
            const int i = seg_start + it * 32 + lane;
            const float px = pts[i * 3 + 0];
            const float py = pts[i * 3 + 1];
            const float pz = pts[i * 3 + 2];

            const float sx = px - cx;
            const float sy = py - cy;
            const float lx = sx * cosa - sy * sina;
            const float ly = sx * sina + sy * cosa;

            const bool in =
                (fabsf(pz - cz) <= hz) &&
                (fabsf(lx) < hx) &&
                (fabsf(ly) < hy);

            const unsigned ball = __ballot_sync(0xffffffffu, in);
            const int r = wcnt + __popc(ball & lmask_lt);
            if (in && r < SSAMP) s_buf[wid][r] = i;
            wcnt += __popc(ball);
        }
        if (lane == 0) s_cnt[wid] = wcnt;
    }
    __syncthreads();

    // --- Merge + wrap resolution ---
    int total = 0;
    int off   = 0;
    #pragma unroll
    for (int w = 0; w < NWARPS; ++w) {
        const int c = s_cnt[w];
        off   += (w < wid) ? c : 0;
        total += c;
    }
    const int cnt = total;
    {
        const int stored = min(s_cnt[wid], SSAMP);
        for (int k = lane; k < stored; k += 32) {
            const int g = off + k;
            if (g < SSAMP) s_src[g] = s_buf[wid][k];
        }
    }
    __syncthreads();
    if (cnt > 0 && cnt < SSAMP) {
        for (int s = cnt + tid; s < SSAMP; s += NTHREADS)
            s_src[s] = s_src[s % cnt];
        __syncthreads();
    }

    // --- Phase 2 (row stride 12 ≡ 0 mod 4 -> pad warp-constant) ---
    float* o = out + (size_t)bm * BOXFLOATS;

    if (cnt == 0) {
        float4 z = make_float4(0.f, 0.f, 0.f, 0.f);
        float4* o4 = (float4*)o;
        for (int i = tid; i < BOXFLOATS / 4; i += NTHREADS)
            __stcs(o4 + i, z);
    } else if (cnt >= NWARPS) {
        // Distinct-source mapping: prepare each row ONCE, store all duplicates.
        const float* fbase = feats + (size_t)b * NPTS * CFEAT;
        const int jmax = min(cnt, SSAMP);
        for (int j = wid; j < jmax; j += NWARPS) {
            const int src = s_src[j];
            const RowCtx r = prepare_row(fbase + (size_t)src * CFEAT,
                                         pts + src * 3, lane);
            for (int s = j; s < SSAMP; s += cnt)
                store_dup_dispatch(o, s * ROWW, r, lane);
        }
    } else {
        // Few distinct rows: per-row mapping keeps all warps busy (L1-resident).
        const float* fbase = feats + (size_t)b * NPTS * CFEAT;
        for (int s = wid; s < SSAMP; s += NWARPS) {
            const int src = s_src[s];
            const RowCtx r = prepare_row(fbase + (size_t)src * CFEAT,
                                         pts + src * 3, lane);
            store_dup_dispatch(o, s * ROWW, r, lane);
        }
    }

    // --- Empty flag ---
    if (tid == 0)
        out[flag_off + bm] = (cnt == 0) ? 1.0f : 0.0f;
}

extern "C" void kernel_launch(void* const* d_in, const int* in_sizes, int n_in,
                              void* d_out, int out_size)
{
    const float* points = (const float*)d_in[0];   // (B, N, 3)
    const float* feats  = (const float*)d_in[1];   // (B, N, C)
    const float* boxes  = (const float*)d_in[2];   // (B, M, 7)
    float* out = (float*)d_out;

    const long long flag_off = (long long)out_size - (long long)NBOX;

    roipool3d_kernel<<<NBOX, NTHREADS>>>(points, feats, boxes, out, flag_off);
}

// round 16
// speedup vs baseline: 1.1336x; 1.0044x over previous
#include <cuda_runtime.h>
#include <cuda_bf16.h>
#include <math.h>

// Problem constants (B, N, M, C, S = 4, 16384, 128, 128, 512)
#define BB    4
#define NPTS  16384
#define MBOX  128
#define CFEAT 128
#define SSAMP 512
#define ROWW  (3 + CFEAT)            // 131 floats per pooled row
#define NBOX  (BB * MBOX)            // 512
#define BOXFLOATS (SSAMP * ROWW)     // 67072 floats per box tile

#define NTHREADS 384
#define NWARPS   (NTHREADS / 32)     // 12
// Contiguous segments, multiples of 128 (4 pts/lane): warps 0-7: 1408 pts
// (11 iters), warps 8-11: 1280 pts (10 iters). 8*1408 + 4*1280 = 16384.
#define SEG_BIG    1408
#define SEG_SMALL  1280

// ---- Lean per-distinct-row context. e1..e3 have lane-0 coord holes pre-merged.
struct RowCtx {
    float4 fv;           // lane's f[4l .. 4l+3]
    float  pc;           // lane<3: own coord (for lead scalars)
    float  e1, e2, e3;   // lane(l-1).fv.{y,z,w}, lane0 = coord{0,1,2}
    float  ty, tz, tw;   // lane31.fv.{y,z,w}  (tail f[125..127])
};

__device__ __forceinline__ RowCtx prepare_row(const float* __restrict__ f,
                                              const float* __restrict__ p,
                                              int lane)
{
    RowCtx r;
    r.fv = __ldg((const float4*)f + lane);
    r.pc = 0.0f;
    if (lane < 3) r.pc = __ldg(p + lane);

    const float uy = __shfl_up_sync(0xffffffffu, r.fv.y, 1);
    const float uz = __shfl_up_sync(0xffffffffu, r.fv.z, 1);
    const float uw = __shfl_up_sync(0xffffffffu, r.fv.w, 1);
    const float c0 = __shfl_sync(0xffffffffu, r.pc, 0);
    const float c1 = __shfl_sync(0xffffffffu, r.pc, 1);
    const float c2 = __shfl_sync(0xffffffffu, r.pc, 2);
    const bool l0 = (lane == 0);
    r.e1 = l0 ? c0 : uy;
    r.e2 = l0 ? c1 : uz;
    r.e3 = l0 ? c2 : uw;
    r.ty = __shfl_sync(0xffffffffu, r.fv.y, 31);
    r.tz = __shfl_sync(0xffffffffu, r.fv.z, 31);
    r.tw = __shfl_sync(0xffffffffu, r.fv.w, 31);
    return r;
}

// ---- One duplicate store: PAD lead scalars + 32 aligned float4 + (3-PAD) tail.
template<int PAD>
__device__ __forceinline__ void store_dup(float* __restrict__ o, int rbase,
                                          const RowCtx& r, int lane)
{
    if (PAD > 0 && lane < PAD)
        __stcs(o + rbase + lane, r.pc);

    float4 v;
    if (PAD == 0) {
        v.x = r.e1; v.y = r.e2; v.z = r.e3; v.w = r.fv.x;
    } else if (PAD == 1) {
        v.x = r.e2; v.y = r.e3; v.z = r.fv.x; v.w = r.fv.y;
    } else if (PAD == 2) {
        v.x = r.e3; v.y = r.fv.x; v.z = r.fv.y; v.w = r.fv.z;
    } else {
        v = r.fv;
    }
    __stcs((float4*)(o + rbase + PAD) + lane, v);

    if (PAD < 3) {
        float tv;
        if (PAD == 0)      tv = (lane == 0) ? r.ty : (lane == 1) ? r.tz : r.tw;
        else if (PAD == 1) tv = (lane == 0) ? r.tz : r.tw;
        else               tv = r.tw;
        if (lane < 3 - PAD)
            __stcs(o + rbase + PAD + 128 + lane, tv);
    }
}

__device__ __forceinline__ void store_dup_dispatch(float* __restrict__ o, int rbase,
                                                   const RowCtx& r, int lane)
{
    switch ((4 - (rbase & 3)) & 3) {   // warp-uniform
    case 0:  store_dup<0>(o, rbase, r, lane); break;
    case 1:  store_dup<1>(o, rbase, r, lane); break;
    case 2:  store_dup<2>(o, rbase, r, lane); break;
    default: store_dup<3>(o, rbase, r, lane); break;
    }
}

__global__ __launch_bounds__(NTHREADS, 4)   // 4 CTAs/SM, single wave, 42-reg budget
void roipool3d_kernel(const float* __restrict__ points,   // (B, N, 3)
                      const float* __restrict__ feats,    // (B, N, C)
                      const float* __restrict__ boxes,    // (B, M, 7)
                      float* __restrict__ out,            // (B,M,S,131) then flags (B,M)
                      long long flag_off)
{
    const int bm = blockIdx.x;
    const int b  = bm >> 7;

    // --- Box parameters ---
    const float* box = boxes + (size_t)bm * 7;
    const float cx = box[0];
    const float cy = box[1];
    const float dz = box[5];
    const float cz = box[2] + 0.5f * dz;
    const float dx = box[3];
    const float dy = box[4];
    const float rz = box[6];
    const float cosa = cosf(-rz);
    const float sina = sinf(-rz);
    const float hx = 0.5f * dx;
    const float hy = 0.5f * dy;
    const float hz = 0.5f * dz;

    __shared__ int s_buf[NWARPS][SSAMP];   // 24 KB: per-warp ordered buffers
    __shared__ int s_cnt[NWARPS];
    __shared__ int s_src[SSAMP];           // wrap-resolved source index per row

    const int tid  = threadIdx.x;
    const int wid  = tid >> 5;
    const int lane = tid & 31;
    const unsigned lmask_lt = (1u << lane) - 1u;

    const float* pts = points + (size_t)b * NPTS * 3;

    // --- Phase 1: float4 loads, 4 points/lane, warp-autonomous compaction ---
    {
        const int seg_start = (wid < 8) ? wid * SEG_BIG
                                        : 8 * SEG_BIG + (wid - 8) * SEG_SMALL;
        const int iters = (wid < 8) ? (SEG_BIG / 128) : (SEG_SMALL / 128);
        const float4* g4 = (const float4*)(pts + seg_start * 3);  // 16B-aligned
        int wcnt = 0;

        #pragma unroll 2
        for (int it = 0; it < iters; ++it) {
            // lane handles points base+4l .. base+4l+3 (index order = lane-major)
            const float4 A  = __ldg(g4 + it * 96 + 3 * lane + 0);  // x0 y0 z0 x1
            const float4 Bv = __ldg(g4 + it * 96 + 3 * lane + 1);  // y1 z1 x2 y2
            const float4 Cv = __ldg(g4 + it * 96 + 3 * lane + 2);  // z2 x3 y3 z3

            bool m0, m1, m2, m3;
            {
                #define BOXTEST(PX, PY, PZ, OUTM) do {                        \
                    const float sx = (PX) - cx;                               \
                    const float sy = (PY) - cy;                               \
                    const float lx = sx * cosa - sy * sina;                   \
                    const float ly = sx * sina + sy * cosa;                   \
                    OUTM = (fabsf((PZ) - cz) <= hz) &&                        \
                           (fabsf(lx) < hx) && (fabsf(ly) < hy);              \
                } while (0)
                BOXTEST(A.x,  A.y,  A.z,  m0);
                BOXTEST(A.w,  Bv.x, Bv.y, m1);
                BOXTEST(Bv.z, Bv.w, Cv.x, m2);
                BOXTEST(Cv.y, Cv.z, Cv.w, m3);
                #undef BOXTEST
            }

            const unsigned b0 = __ballot_sync(0xffffffffu, m0);
            const unsigned b1 = __ballot_sync(0xffffffffu, m1);
            const unsigned b2 = __ballot_sync(0xffffffffu, m2);
            const unsigned b3 = __ballot_sync(0xffffffffu, m3);

            const int pre = __popc(b0 & lmask_lt) + __popc(b1 & lmask_lt)
                          + __popc(b2 & lmask_lt) + __popc(b3 & lmask_lt);
            const int idx = seg_start + it * 128 + 4 * lane;

            int rk = wcnt + pre;
            if (m0 && rk < SSAMP) s_buf[wid][rk] = idx + 0;
            rk += m0;
            if (m1 && rk < SSAMP) s_buf[wid][rk] = idx + 1;
            rk += m1;
            if (m2 && rk < SSAMP) s_buf[wid][rk] = idx + 2;
            rk += m2;
            if (m3 && rk < SSAMP) s_buf[wid][rk] = idx + 3;

            wcnt += __popc(b0) + __popc(b1) + __popc(b2) + __popc(b3);
        }
        if (lane == 0) s_cnt[wid] = wcnt;
    }
    __syncthreads();

    // --- Merge + wrap resolution ---
    int total = 0;
    int off   = 0;
    #pragma unroll
    for (int w = 0; w < NWARPS; ++w) {
        const int c = s_cnt[w];
        off   += (w < wid) ? c : 0;
        total += c;
    }
    const int cnt = total;
    {
        const int stored = min(s_cnt[wid], SSAMP);
        for (int k = lane; k < stored; k += 32) {
            const int g = off + k;
            if (g < SSAMP) s_src[g] = s_buf[wid][k];
        }
    }
    __syncthreads();
    if (cnt > 0 && cnt < SSAMP) {
        for (int s = cnt + tid; s < SSAMP; s += NTHREADS)
            s_src[s] = s_src[s % cnt];
        __syncthreads();
    }

    // --- Phase 2 (row stride 12 ≡ 0 mod 4 -> pad warp-constant per loop) ---
    float* o = out + (size_t)bm * BOXFLOATS;

    if (cnt == 0) {
        float4 z = make_float4(0.f, 0.f, 0.f, 0.f);
        float4* o4 = (float4*)o;
        for (int i = tid; i < BOXFLOATS / 4; i += NTHREADS)
            __stcs(o4 + i, z);
    } else if (cnt >= NWARPS) {
        // Distinct-source mapping: prepare each row ONCE, store all duplicates.
        const float* fbase = feats + (size_t)b * NPTS * CFEAT;
        const int jmax = min(cnt, SSAMP);
        for (int j = wid; j < jmax; j += NWARPS) {
            const int src = s_src[j];
            const RowCtx r = prepare_row(fbase + (size_t)src * CFEAT,
                                         pts + src * 3, lane);
            for (int s = j; s < SSAMP; s += cnt)
                store_dup_dispatch(o, s * ROWW, r, lane);
        }
    } else {
        // Few distinct rows: per-row mapping keeps all warps busy (L1-resident).
        const float* fbase = feats + (size_t)b * NPTS * CFEAT;
        for (int s = wid; s < SSAMP; s += NWARPS) {
            const int src = s_src[s];
            const RowCtx r = prepare_row(fbase + (size_t)src * CFEAT,
                                         pts + src * 3, lane);
            store_dup_dispatch(o, s * ROWW, r, lane);
        }
    }

    // --- Empty flag ---
    if (tid == 0)
        out[flag_off + bm] = (cnt == 0) ? 1.0f : 0.0f;
}

extern "C" void kernel_launch(void* const* d_in, const int* in_sizes, int n_in,
                              void* d_out, int out_size)
{
    const float* points = (const float*)d_in[0];   // (B, N, 3)
    const float* feats  = (const float*)d_in[1];   // (B, N, C)
    const float* boxes  = (const float*)d_in[2];   // (B, M, 7)
    float* out = (float*)d_out;

    const long long flag_off = (long long)out_size - (long long)NBOX;

    roipool3d_kernel<<<NBOX, NTHREADS>>>(points, feats, boxes, out, flag_off);
}